// round 4
// baseline (speedup 1.0000x reference)
#include <cuda_runtime.h>
#include <cuda_bf16.h>
#include <cfloat>

// SpatialAttentionModule: x[16,64,256,256] f32
//   avg = mean_c(x), mx = max_c(x); mask = sigmoid(conv7x7_2to1([avg;mx]) + b)
//   out = x * mask
//
// K1 reduce: channel mean/max -> g_avg/g_max (8 MB, L2-resident). MLP 16.
// K2 conv:   7x7 conv + sigmoid -> g_mask (4 MB, L2-resident). Tiny.
// K3 scale:  pure stream, out = x * mask. No SMEM/barriers -> max DRAM duty.

#define B_  16
#define C_  64
#define H_  256
#define W_  256
#define HW  (H_ * W_)
#define HW4 (HW / 4)               // 16384 float4 per (b,c) plane
#define KS  7
#define PADK 3
#define WPAD (W_ + 2 * PADK)       // 262

__device__ float g_avg[B_ * HW];
__device__ float g_max[B_ * HW];
__device__ float g_mask[B_ * HW];

__global__ __launch_bounds__(256) void reduce_kernel(const float4* __restrict__ x) {
    int g  = blockIdx.x * 256 + threadIdx.x;     // 0 .. B_*HW4-1
    int b  = g >> 14;
    int hw = g & (HW4 - 1);

    const float4* p = x + ((size_t)b * C_) * HW4 + hw;

    float4 s = make_float4(0.f, 0.f, 0.f, 0.f);
    float4 m = make_float4(-FLT_MAX, -FLT_MAX, -FLT_MAX, -FLT_MAX);

    #pragma unroll 16
    for (int c = 0; c < C_; ++c) {
        float4 v = __ldcs(p + (size_t)c * HW4);
        s.x += v.x; s.y += v.y; s.z += v.z; s.w += v.w;
        m.x = fmaxf(m.x, v.x); m.y = fmaxf(m.y, v.y);
        m.z = fmaxf(m.z, v.z); m.w = fmaxf(m.w, v.w);
    }

    const float inv = 1.0f / (float)C_;
    float4 a = make_float4(s.x * inv, s.y * inv, s.z * inv, s.w * inv);
    reinterpret_cast<float4*>(g_avg)[g] = a;   // default policy: keep in L2
    reinterpret_cast<float4*>(g_max)[g] = m;
}

// One block per (b, h) row; 256 threads = 1 pixel each.
__global__ __launch_bounds__(256) void conv_mask_kernel(const float* __restrict__ conv_w,
                                                        const float* __restrict__ conv_b) {
    __shared__ float sw[2 * KS * KS];
    __shared__ float sm[2 * KS * WPAD];

    const int tid = threadIdx.x;
    const int b   = blockIdx.x >> 8;
    const int h   = blockIdx.x & (H_ - 1);

    if (tid < 2 * KS * KS) sw[tid] = __ldg(&conv_w[tid]);

    for (int i = tid; i < 2 * KS * WPAD; i += 256) {
        int ic = i / (KS * WPAD);
        int r  = i - ic * (KS * WPAD);
        int kh = r / WPAD;
        int wp = r - kh * WPAD;
        int wc = wp - PADK;
        int hh = h + kh - PADK;
        float v = 0.f;
        if (hh >= 0 && hh < H_ && wc >= 0 && wc < W_) {
            const float* plane = ic ? g_max : g_avg;
            v = __ldg(&plane[((size_t)b * H_ + hh) * W_ + wc]);   // L2 hit
        }
        sm[i] = v;
    }
    __syncthreads();

    float acc = __ldg(&conv_b[0]);
    #pragma unroll
    for (int ic = 0; ic < 2; ++ic) {
        #pragma unroll
        for (int kh = 0; kh < KS; ++kh) {
            const float* row = &sm[(ic * KS + kh) * WPAD + tid];
            const float* wr  = &sw[(ic * KS + kh) * KS];
            #pragma unroll
            for (int kw = 0; kw < KS; ++kw)
                acc += row[kw] * wr[kw];
        }
    }
    g_mask[((size_t)b * H_ + h) * W_ + tid] = 1.0f / (1.0f + __expf(-acc));
}

// Pure stream: thread -> (b, cg, hw4). Reads mask float4 once (L2),
// then 8 independent channel load/mul/store float4 pairs.
__global__ __launch_bounds__(256) void scale_kernel(const float4* __restrict__ x,
                                                    float4* __restrict__ out) {
    int g  = blockIdx.x * 256 + threadIdx.x;   // 0 .. B_*8*HW4-1 (2,097,152)
    int b  = g >> 17;                          // / (8*HW4)
    int r  = g & ((8 * HW4) - 1);
    int cg = r >> 14;                          // channel group 0..7
    int hw = r & (HW4 - 1);

    const float4 mk = __ldg(&reinterpret_cast<const float4*>(g_mask)[b * HW4 + hw]);

    size_t base = ((size_t)b * C_ + cg * 8) * HW4 + hw;

    #pragma unroll
    for (int i = 0; i < 8; ++i) {
        size_t idx = base + (size_t)i * HW4;
        float4 v = __ldcs(&x[idx]);
        v.x *= mk.x; v.y *= mk.y; v.z *= mk.z; v.w *= mk.w;
        __stcs(&out[idx], v);
    }
}

extern "C" void kernel_launch(void* const* d_in, const int* in_sizes, int n_in,
                              void* d_out, int out_size) {
    const float* x      = (const float*)d_in[0];
    const float* conv_w = (const float*)d_in[1];
    const float* conv_b = (const float*)d_in[2];
    float* out          = (float*)d_out;

    reduce_kernel<<<(B_ * HW4) / 256, 256>>>((const float4*)x);
    conv_mask_kernel<<<B_ * H_, 256>>>(conv_w, conv_b);
    scale_kernel<<<(B_ * 8 * HW4) / 256, 256>>>((const float4*)x, (float4*)out);
}